// round 10
// baseline (speedup 1.0000x reference)
#include <cuda_runtime.h>
#include <math.h>
#include <stdint.h>

#define HG   64      // GRU hidden
#define HID  128
#define APPD 512
#define TT   16      // timesteps
#define ROWS 64      // rows per CTA
#define NTHR 256     // 8 warps
#define XS   34      // x smem stride (floats)
#define HS   68      // h smem stride (68 mod 32 = 4 -> conflict-free A-frag LDS)

// Scratch for traj_feat [B,128] (device global array: the sanctioned scratch mechanism)
__device__ float g_tfeat[131072 * HID];

static __device__ __forceinline__ uint32_t f2tf(float f) {
    uint32_t u; asm("cvt.rna.tf32.f32 %0, %1;" : "=r"(u) : "f"(f)); return u;
}
static __device__ __forceinline__ float tanh_ap(float x) {
    float y; asm("tanh.approx.f32 %0, %1;" : "=f"(y) : "f"(x)); return y;
}
static __device__ __forceinline__ float sig_ap(float x) {
    return 0.5f + 0.5f * tanh_ap(0.5f * x);
}
// D += A(16x8 tf32,row) * B(8x8 tf32,col)   (f32 accum)
static __device__ __forceinline__ void mma8(float c[4], const uint32_t a[4], const uint32_t b[2]) {
    asm volatile("mma.sync.aligned.m16n8k8.row.col.f32.tf32.tf32.f32 "
                 "{%0,%1,%2,%3}, {%4,%5,%6,%7}, {%8,%9}, {%0,%1,%2,%3};\n"
                 : "+f"(c[0]), "+f"(c[1]), "+f"(c[2]), "+f"(c[3])
                 : "r"(a[0]), "r"(a[1]), "r"(a[2]), "r"(a[3]),
                   "r"(b[0]), "r"(b[1]));
}

// ===================== Kernel A: GRU (16 steps) + traj projection =====================
__global__ void __launch_bounds__(NTHR, 1)
gru_traj_kernel(const float* __restrict__ cent,
                const float* __restrict__ Wih, const float* __restrict__ Whh,
                const float* __restrict__ bih, const float* __restrict__ bhh,
                const float* __restrict__ Wt,  const float* __restrict__ bt,
                int B)
{
    __shared__ __align__(16) float    xs[ROWS * XS];
    __shared__ __align__(16) uint32_t hs[2][ROWS * HS];

    const int tid  = threadIdx.x;
    const int w    = tid >> 5;
    const int lane = tid & 31;
    const int q    = lane >> 2;   // group id (row within frag)
    const int p    = lane & 3;    // thread-in-group
    const int base = blockIdx.x * ROWS;

    // ---- load centroid history into smem: xs[row*XS + t*2 + d] ----
    #pragma unroll
    for (int j = 0; j < 2; j++) {
        int i   = tid + j * NTHR;          // float4 index, 512 total
        int row = i >> 3, c4 = i & 7;
        int gr  = min(base + row, B - 1);
        float4 v = *(const float4*)(cent + (size_t)gr * (TT * 2) + c4 * 4);
        xs[row * XS + c4 * 4 + 0] = v.x;
        xs[row * XS + c4 * 4 + 1] = v.y;
        xs[row * XS + c4 * 4 + 2] = v.z;
        xs[row * XS + c4 * 4 + 3] = v.w;
    }
    // ---- zero h buffer 0 ----
    for (int i = tid; i < ROWS * HS; i += NTHR) hs[0][i] = 0u;

    // ---- per-thread gate constants for the 2 owned output cols (2p, 2p+1) ----
    float wi0[3][2], wi1[3][2], bi[3][2], bh[3][2];
    #pragma unroll
    for (int ty = 0; ty < 3; ty++)
        #pragma unroll
        for (int e = 0; e < 2; e++) {
            int g = ty * HG + w * 8 + 2 * p + e;
            wi0[ty][e] = Wih[g * 2 + 0];
            wi1[ty][e] = Wih[g * 2 + 1];
            bi[ty][e]  = bih[g];
            bh[ty][e]  = bhh[g];
        }

    // ---- W_hh B-fragments held in registers across all 16 steps ----
    uint32_t Br[8][2], Bz[8][2], Bn[8][2];
    #pragma unroll
    for (int kt = 0; kt < 8; kt++) {
        int k  = kt * 8 + p;
        int nr = 0 * HG + w * 8 + q;
        int nz = 1 * HG + w * 8 + q;
        int nn = 2 * HG + w * 8 + q;
        Br[kt][0] = f2tf(Whh[nr * HG + k]);  Br[kt][1] = f2tf(Whh[nr * HG + k + 4]);
        Bz[kt][0] = f2tf(Whh[nz * HG + k]);  Bz[kt][1] = f2tf(Whh[nz * HG + k + 4]);
        Bn[kt][0] = f2tf(Whh[nn * HG + k]);  Bn[kt][1] = f2tf(Whh[nn * HG + k + 4]);
    }

    float hreg[4][4];
    #pragma unroll
    for (int m = 0; m < 4; m++)
        #pragma unroll
        for (int e = 0; e < 4; e++) hreg[m][e] = 0.f;

    __syncthreads();

    // ---- 16 GRU steps ----
    for (int t = 0; t < TT; t++) {
        const uint32_t* hc  = hs[t & 1];
        uint32_t*       hnx = hs[(t + 1) & 1];

        float cr[4][4], cz[4][4], cn[4][4];
        #pragma unroll
        for (int m = 0; m < 4; m++)
            #pragma unroll
            for (int e = 0; e < 4; e++) { cr[m][e] = 0.f; cz[m][e] = 0.f; cn[m][e] = 0.f; }

        #pragma unroll
        for (int kt = 0; kt < 8; kt++) {
            #pragma unroll
            for (int m = 0; m < 4; m++) {
                uint32_t a[4];
                int r0 = m * 16 + q;
                int k0 = kt * 8 + p;
                a[0] = hc[r0 * HS + k0];
                a[1] = hc[(r0 + 8) * HS + k0];
                a[2] = hc[r0 * HS + k0 + 4];
                a[3] = hc[(r0 + 8) * HS + k0 + 4];
                mma8(cr[m], a, Br[kt]);
                mma8(cz[m], a, Bz[kt]);
                mma8(cn[m], a, Bn[kt]);
            }
        }

        // ---- activations (register elementwise; C-frag layout) ----
        #pragma unroll
        for (int m = 0; m < 4; m++) {
            int rlo = m * 16 + q;
            float2 xlo = *(const float2*)(xs + rlo * XS + t * 2);
            float2 xhi = *(const float2*)(xs + (rlo + 8) * XS + t * 2);
            #pragma unroll
            for (int e2 = 0; e2 < 4; e2++) {
                int hi = e2 >> 1;          // row +8 half
                int je = e2 & 1;           // col 2p / 2p+1
                float x0 = hi ? xhi.x : xlo.x;
                float x1 = hi ? xhi.y : xlo.y;
                float ghr = cr[m][e2] + bh[0][je];
                float ghz = cz[m][e2] + bh[1][je];
                float ghn = cn[m][e2] + bh[2][je];
                float xr  = fmaf(wi1[0][je], x1, fmaf(wi0[0][je], x0, bi[0][je]));
                float xz  = fmaf(wi1[1][je], x1, fmaf(wi0[1][je], x0, bi[1][je]));
                float xn  = fmaf(wi1[2][je], x1, fmaf(wi0[2][je], x0, bi[2][je]));
                float r   = sig_ap(xr + ghr);
                float z   = sig_ap(xz + ghz);
                float nv  = tanh_ap(fmaf(r, ghn, xn));
                float hp  = hreg[m][e2];
                float hv  = fmaf(z, hp - nv, nv);   // (1-z)*n + z*h
                hreg[m][e2] = hv;
                int row = rlo + (hi ? 8 : 0);
                int col = w * 8 + 2 * p + je;
                hnx[row * HS + col] = f2tf(hv);
            }
        }
        __syncthreads();
    }

    // ---- traj projection: tfeat[64,128] = h_last @ Wt^T + bt ----
    const uint32_t* hl = hs[0];   // after 16 steps h_last is in buffer 0

    uint32_t Bt[8][2][2];
    #pragma unroll
    for (int kt = 0; kt < 8; kt++)
        #pragma unroll
        for (int n2 = 0; n2 < 2; n2++) {
            int n = w * 16 + n2 * 8 + q;
            int k = kt * 8 + p;
            Bt[kt][n2][0] = f2tf(Wt[n * HG + k]);
            Bt[kt][n2][1] = f2tf(Wt[n * HG + k + 4]);
        }

    float ct[4][2][4];
    #pragma unroll
    for (int m = 0; m < 4; m++)
        #pragma unroll
        for (int n2 = 0; n2 < 2; n2++)
            #pragma unroll
            for (int e = 0; e < 4; e++) ct[m][n2][e] = 0.f;

    #pragma unroll
    for (int kt = 0; kt < 8; kt++) {
        #pragma unroll
        for (int m = 0; m < 4; m++) {
            uint32_t a[4];
            int r0 = m * 16 + q;
            int k0 = kt * 8 + p;
            a[0] = hl[r0 * HS + k0];
            a[1] = hl[(r0 + 8) * HS + k0];
            a[2] = hl[r0 * HS + k0 + 4];
            a[3] = hl[(r0 + 8) * HS + k0 + 4];
            mma8(ct[m][0], a, Bt[kt][0]);
            mma8(ct[m][1], a, Bt[kt][1]);
        }
    }

    float btv[2][2];
    #pragma unroll
    for (int n2 = 0; n2 < 2; n2++)
        #pragma unroll
        for (int e = 0; e < 2; e++) btv[n2][e] = bt[w * 16 + n2 * 8 + 2 * p + e];

    // ---- stage tfeat through smem (reuse hs) for coalesced global stores ----
    __syncthreads();                       // all hl reads done before overwrite
    float* hf = (float*)hs;                // [2][64*68] as float
    #pragma unroll
    for (int m = 0; m < 4; m++)
        #pragma unroll
        for (int n2 = 0; n2 < 2; n2++)
            #pragma unroll
            for (int e2 = 0; e2 < 4; e2++) {
                int row = m * 16 + q + ((e2 & 2) ? 8 : 0);
                int col = w * 16 + n2 * 8 + 2 * p + (e2 & 1);
                float v = ct[m][n2][e2] + btv[n2][e2 & 1];
                hf[(col >> 6) * (ROWS * HS) + row * HS + (col & 63)] = v;
            }
    __syncthreads();
    #pragma unroll
    for (int j = 0; j < 8; j++) {
        int i = tid + j * NTHR;            // 2048 float4
        int row = i >> 5, c4 = i & 31;
        int col = c4 * 4;
        float4 v = *(const float4*)(hf + (col >> 6) * (ROWS * HS) + row * HS + (col & 63));
        int gr = base + row;
        if (gr < B) *(float4*)(g_tfeat + (size_t)gr * HID + col) = v;
    }
}

// ===================== Kernel B: appear_proj + fuse + GELU =====================
__global__ void __launch_bounds__(NTHR, 1)
appear_fuse_kernel(const float* __restrict__ app,
                   const float* __restrict__ Wa, const float* __restrict__ ba,
                   const float* __restrict__ Wf, const float* __restrict__ bf,
                   float* __restrict__ out, int B)
{
    __shared__ __align__(16) uint32_t sm[2][ROWS * HS];   // 34816 B

    const int tid  = threadIdx.x;
    const int w    = tid >> 5;
    const int lane = tid & 31;
    const int q    = lane >> 2;
    const int p    = lane & 3;
    const int base = blockIdx.x * ROWS;

    // per-thread load slots for a 64x64 chunk (4 float4 each)
    const int lrow = tid >> 4;            // NOTE: i = tid + j*256 -> row = i>>4
    // (recomputed per j below)

    float4 pre[4];
    // ---- prefetch chunk 0 ----
    #pragma unroll
    for (int j = 0; j < 4; j++) {
        int i = tid + j * NTHR; int row = i >> 4, c4 = i & 15;
        int gr = min(base + row, B - 1);
        pre[j] = *(const float4*)(app + (size_t)gr * APPD + 0 * 64 + c4 * 4);
    }
    #pragma unroll
    for (int j = 0; j < 4; j++) {
        int i = tid + j * NTHR; int row = i >> 4, c4 = i & 15;
        uint32_t* d = &sm[0][row * HS + c4 * 4];
        d[0] = f2tf(pre[j].x); d[1] = f2tf(pre[j].y);
        d[2] = f2tf(pre[j].z); d[3] = f2tf(pre[j].w);
    }
    #pragma unroll
    for (int j = 0; j < 4; j++) {
        int i = tid + j * NTHR; int row = i >> 4, c4 = i & 15;
        int gr = min(base + row, B - 1);
        pre[j] = *(const float4*)(app + (size_t)gr * APPD + 1 * 64 + c4 * 4);
    }
    __syncthreads();

    float cf[4][2][4];
    #pragma unroll
    for (int m = 0; m < 4; m++)
        #pragma unroll
        for (int n2 = 0; n2 < 2; n2++)
            #pragma unroll
            for (int e = 0; e < 4; e++) cf[m][n2][e] = 0.f;

    // ---- phase 1: appear GEMM over 8 chunks of K=64, double-buffered ----
    for (int c = 0; c < 8; c++) {
        if (c + 1 < 8) {
            #pragma unroll
            for (int j = 0; j < 4; j++) {
                int i = tid + j * NTHR; int row = i >> 4, c4 = i & 15;
                uint32_t* d = &sm[(c + 1) & 1][row * HS + c4 * 4];
                d[0] = f2tf(pre[j].x); d[1] = f2tf(pre[j].y);
                d[2] = f2tf(pre[j].z); d[3] = f2tf(pre[j].w);
            }
            if (c + 2 < 8) {
                #pragma unroll
                for (int j = 0; j < 4; j++) {
                    int i = tid + j * NTHR; int row = i >> 4, c4 = i & 15;
                    int gr = min(base + row, B - 1);
                    pre[j] = *(const float4*)(app + (size_t)gr * APPD + (c + 2) * 64 + c4 * 4);
                }
            }
        }
        const uint32_t* hb = sm[c & 1];
        #pragma unroll
        for (int kt = 0; kt < 8; kt++) {
            uint32_t Bw[2][2];
            #pragma unroll
            for (int n2 = 0; n2 < 2; n2++) {
                int n = w * 16 + n2 * 8 + q;
                int k = c * 64 + kt * 8 + p;
                Bw[n2][0] = f2tf(Wa[n * APPD + k]);
                Bw[n2][1] = f2tf(Wa[n * APPD + k + 4]);
            }
            #pragma unroll
            for (int m = 0; m < 4; m++) {
                uint32_t a[4];
                int r0 = m * 16 + q;
                int k0 = kt * 8 + p;
                a[0] = hb[r0 * HS + k0];
                a[1] = hb[(r0 + 8) * HS + k0];
                a[2] = hb[r0 * HS + k0 + 4];
                a[3] = hb[(r0 + 8) * HS + k0 + 4];
                mma8(cf[m][0], a, Bw[0]);
                mma8(cf[m][1], a, Bw[1]);
            }
        }
        __syncthreads();
    }

    // ---- stage afeat (+ba) as tf32 into sm halves ----
    float bav[2][2];
    #pragma unroll
    for (int n2 = 0; n2 < 2; n2++)
        #pragma unroll
        for (int e = 0; e < 2; e++) bav[n2][e] = ba[w * 16 + n2 * 8 + 2 * p + e];

    #pragma unroll
    for (int m = 0; m < 4; m++)
        #pragma unroll
        for (int n2 = 0; n2 < 2; n2++)
            #pragma unroll
            for (int e2 = 0; e2 < 4; e2++) {
                int row = m * 16 + q + ((e2 & 2) ? 8 : 0);
                int col = w * 16 + n2 * 8 + 2 * p + (e2 & 1);
                sm[col >> 6][row * HS + (col & 63)] = f2tf(cf[m][n2][e2] + bav[n2][e2 & 1]);
            }
    __syncthreads();

    // ---- phase 2: fuse GEMM, pass 1 (afeat, Wf cols 0..127) ----
    float cf2[4][2][4];
    #pragma unroll
    for (int m = 0; m < 4; m++)
        #pragma unroll
        for (int n2 = 0; n2 < 2; n2++)
            #pragma unroll
            for (int e = 0; e < 4; e++) cf2[m][n2][e] = 0.f;

    #pragma unroll
    for (int pass = 0; pass < 2; pass++) {
        int woff = pass * HID;
        #pragma unroll
        for (int kt = 0; kt < 16; kt++) {
            const uint32_t* hb = sm[kt >> 3];
            int kk = (kt & 7) * 8;
            uint32_t Bw[2][2];
            #pragma unroll
            for (int n2 = 0; n2 < 2; n2++) {
                int n = w * 16 + n2 * 8 + q;
                int k = woff + kt * 8 + p;
                Bw[n2][0] = f2tf(Wf[n * (2 * HID) + k]);
                Bw[n2][1] = f2tf(Wf[n * (2 * HID) + k + 4]);
            }
            #pragma unroll
            for (int m = 0; m < 4; m++) {
                uint32_t a[4];
                int r0 = m * 16 + q;
                int k0 = kk + p;
                a[0] = hb[r0 * HS + k0];
                a[1] = hb[(r0 + 8) * HS + k0];
                a[2] = hb[r0 * HS + k0 + 4];
                a[3] = hb[(r0 + 8) * HS + k0 + 4];
                mma8(cf2[m][0], a, Bw[0]);
                mma8(cf2[m][1], a, Bw[1]);
            }
        }
        if (pass == 0) {
            // load tfeat tile into sm for pass 2
            __syncthreads();
            #pragma unroll
            for (int j = 0; j < 8; j++) {
                int i = tid + j * NTHR;            // 2048 float4
                int row = i >> 5, c4 = i & 31;
                int col = c4 * 4;
                int gr = min(base + row, B - 1);
                float4 v = *(const float4*)(g_tfeat + (size_t)gr * HID + col);
                uint32_t* d = &sm[col >> 6][row * HS + (col & 63)];
                d[0] = f2tf(v.x); d[1] = f2tf(v.y);
                d[2] = f2tf(v.z); d[3] = f2tf(v.w);
            }
            __syncthreads();
        }
    }

    // ---- bias + exact GELU, stage to smem, coalesced store ----
    float bfv[2][2];
    #pragma unroll
    for (int n2 = 0; n2 < 2; n2++)
        #pragma unroll
        for (int e = 0; e < 2; e++) bfv[n2][e] = bf[w * 16 + n2 * 8 + 2 * p + e];

    __syncthreads();                       // pass-2 reads done before overwrite
    float* smf = (float*)sm;
    #pragma unroll
    for (int m = 0; m < 4; m++)
        #pragma unroll
        for (int n2 = 0; n2 < 2; n2++)
            #pragma unroll
            for (int e2 = 0; e2 < 4; e2++) {
                int row = m * 16 + q + ((e2 & 2) ? 8 : 0);
                int col = w * 16 + n2 * 8 + 2 * p + (e2 & 1);
                float x = cf2[m][n2][e2] + bfv[n2][e2 & 1];
                float y = 0.5f * x * (1.0f + erff(x * 0.70710678118654752f));
                smf[(col >> 6) * (ROWS * HS) + row * HS + (col & 63)] = y;
            }
    __syncthreads();
    #pragma unroll
    for (int j = 0; j < 8; j++) {
        int i = tid + j * NTHR;
        int row = i >> 5, c4 = i & 31;
        int col = c4 * 4;
        float4 v = *(const float4*)(smf + (col >> 6) * (ROWS * HS) + row * HS + (col & 63));
        int gr = base + row;
        if (gr < B) *(float4*)(out + (size_t)gr * HID + col) = v;
    }
}

extern "C" void kernel_launch(void* const* d_in, const int* in_sizes, int n_in,
                              void* d_out, int out_size) {
    const float* app  = (const float*)d_in[0];   // [B,512]
    const float* cent = (const float*)d_in[1];   // [B,16,2]
    const float* Wih  = (const float*)d_in[2];   // [192,2]
    const float* Whh  = (const float*)d_in[3];   // [192,64]
    const float* bih  = (const float*)d_in[4];   // [192]
    const float* bhh  = (const float*)d_in[5];   // [192]
    const float* Wt   = (const float*)d_in[6];   // [128,64]
    const float* bt   = (const float*)d_in[7];   // [128]
    const float* Wa   = (const float*)d_in[8];   // [128,512]
    const float* ba   = (const float*)d_in[9];   // [128]
    const float* Wf   = (const float*)d_in[10];  // [128,256]
    const float* bf   = (const float*)d_in[11];  // [128]
    float* out = (float*)d_out;

    int B = in_sizes[0] / APPD;
    int nblk = (B + ROWS - 1) / ROWS;

    gru_traj_kernel<<<nblk, NTHR>>>(cent, Wih, Whh, bih, bhh, Wt, bt, B);
    appear_fuse_kernel<<<nblk, NTHR>>>(app, Wa, ba, Wf, bf, out, B);
}

// round 17
// speedup vs baseline: 1.0065x; 1.0065x over previous
#include <cuda_runtime.h>
#include <math.h>
#include <stdint.h>

#define HG   64      // GRU hidden
#define HID  128
#define APPD 512
#define TT   16      // timesteps
#define ROWS 64      // rows per CTA
#define NTHR 256     // 8 warps
#define XS   34      // x smem stride (floats)
#define HS   68      // h/feat smem stride (words; even -> 8B-aligned LDS.64)

// Scratch (device globals: the sanctioned scratch mechanism)
__device__ float    g_tfeat[131072 * HID];          // traj_feat [B,128]
__device__ uint32_t g_wa_sw[HID * APPD];            // swizzled Wa fragments (tf32 bits)
__device__ uint32_t g_wf_sw[HID * 2 * HID];         // swizzled Wf fragments (tf32 bits)

static __device__ __forceinline__ uint32_t f2tf(float f) {
    uint32_t u; asm("cvt.rna.tf32.f32 %0, %1;" : "=r"(u) : "f"(f)); return u;
}
static __device__ __forceinline__ float tanh_ap(float x) {
    float y; asm("tanh.approx.f32 %0, %1;" : "=f"(y) : "f"(x)); return y;
}
static __device__ __forceinline__ float sig_ap(float x) {
    return 0.5f + 0.5f * tanh_ap(0.5f * x);
}
// D += A(16x8 tf32,row) * B(8x8 tf32,col)   (f32 accum)
// NOTE: permuted k-labelling: thread p's two k-lanes carry logical
// k = k0+2p and k0+2p+1 on BOTH A and B sides (reduction is order-invariant).
static __device__ __forceinline__ void mma8(float c[4], const uint32_t a[4], const uint32_t b[2]) {
    asm volatile("mma.sync.aligned.m16n8k8.row.col.f32.tf32.tf32.f32 "
                 "{%0,%1,%2,%3}, {%4,%5,%6,%7}, {%8,%9}, {%0,%1,%2,%3};\n"
                 : "+f"(c[0]), "+f"(c[1]), "+f"(c[2]), "+f"(c[3])
                 : "r"(a[0]), "r"(a[1]), "r"(a[2]), "r"(a[3]),
                   "r"(b[0]), "r"(b[1]));
}

// ============ weight swizzle prep: fragment-ordered tf32 weights ============
// Writes DIRECTLY to the __device__ globals (no cudaGetSymbolAddress on host).
// dst index = ((ko*4 + nw)*2 + n2p)*128 + lane*4 + r
//   q=lane>>2, p=lane&3
//   n = nw*32 + (n2p*2 + (r>>1))*8 + q
//   k = ko*8 + 2*p + (r&1)          (permuted-k labelling)
__global__ void swizzle_wa_kernel(const float* __restrict__ W)
{
    int i = blockIdx.x * 256 + threadIdx.x;
    if (i >= HID * APPD) return;
    int r    = i & 3;
    int lane = (i >> 2) & 31;
    int n2p  = (i >> 7) & 1;
    int nw   = (i >> 8) & 3;
    int ko   = i >> 10;
    int q = lane >> 2, p = lane & 3;
    int n = nw * 32 + (n2p * 2 + (r >> 1)) * 8 + q;
    int k = ko * 8 + 2 * p + (r & 1);
    g_wa_sw[i] = f2tf(W[n * APPD + k]);
}
__global__ void swizzle_wf_kernel(const float* __restrict__ W)
{
    int i = blockIdx.x * 256 + threadIdx.x;
    if (i >= HID * 2 * HID) return;
    int r    = i & 3;
    int lane = (i >> 2) & 31;
    int n2p  = (i >> 7) & 1;
    int nw   = (i >> 8) & 3;
    int ko   = i >> 10;
    int q = lane >> 2, p = lane & 3;
    int n = nw * 32 + (n2p * 2 + (r >> 1)) * 8 + q;
    int k = ko * 8 + 2 * p + (r & 1);
    g_wf_sw[i] = f2tf(W[n * (2 * HID) + k]);
}

// ===================== Kernel A: GRU (16 steps) + traj projection =====================
__global__ void __launch_bounds__(NTHR, 1)
gru_traj_kernel(const float* __restrict__ cent,
                const float* __restrict__ Wih, const float* __restrict__ Whh,
                const float* __restrict__ bih, const float* __restrict__ bhh,
                const float* __restrict__ Wt,  const float* __restrict__ bt,
                int B)
{
    __shared__ __align__(16) float    xs[ROWS * XS];
    __shared__ __align__(16) uint32_t hs[2][ROWS * HS];

    const int tid  = threadIdx.x;
    const int w    = tid >> 5;
    const int lane = tid & 31;
    const int q    = lane >> 2;
    const int p    = lane & 3;
    const int base = blockIdx.x * ROWS;

    // ---- load centroid history into smem: xs[row*XS + t*2 + d] ----
    #pragma unroll
    for (int j = 0; j < 2; j++) {
        int i   = tid + j * NTHR;
        int row = i >> 3, c4 = i & 7;
        int gr  = min(base + row, B - 1);
        float4 v = *(const float4*)(cent + (size_t)gr * (TT * 2) + c4 * 4);
        xs[row * XS + c4 * 4 + 0] = v.x;
        xs[row * XS + c4 * 4 + 1] = v.y;
        xs[row * XS + c4 * 4 + 2] = v.z;
        xs[row * XS + c4 * 4 + 3] = v.w;
    }
    for (int i = tid; i < ROWS * HS; i += NTHR) hs[0][i] = 0u;

    // ---- per-thread gate constants for the 2 owned output cols (2p, 2p+1) ----
    float wi0[3][2], wi1[3][2], bi[3][2], bh[3][2];
    #pragma unroll
    for (int ty = 0; ty < 3; ty++)
        #pragma unroll
        for (int e = 0; e < 2; e++) {
            int g = ty * HG + w * 8 + 2 * p + e;
            wi0[ty][e] = Wih[g * 2 + 0];
            wi1[ty][e] = Wih[g * 2 + 1];
            bi[ty][e]  = bih[g];
            bh[ty][e]  = bhh[g];
        }

    // ---- W_hh B-fragments (permuted k) held in registers across all steps ----
    uint32_t Br[8][2], Bz[8][2], Bn[8][2];
    #pragma unroll
    for (int kt = 0; kt < 8; kt++) {
        int k  = kt * 8 + 2 * p;                 // permuted-k: lanes k, k+1
        int nr = 0 * HG + w * 8 + q;
        int nz = 1 * HG + w * 8 + q;
        int nn = 2 * HG + w * 8 + q;
        Br[kt][0] = f2tf(Whh[nr * HG + k]);  Br[kt][1] = f2tf(Whh[nr * HG + k + 1]);
        Bz[kt][0] = f2tf(Whh[nz * HG + k]);  Bz[kt][1] = f2tf(Whh[nz * HG + k + 1]);
        Bn[kt][0] = f2tf(Whh[nn * HG + k]);  Bn[kt][1] = f2tf(Whh[nn * HG + k + 1]);
    }

    float hreg[4][4];
    #pragma unroll
    for (int m = 0; m < 4; m++)
        #pragma unroll
        for (int e = 0; e < 4; e++) hreg[m][e] = 0.f;

    __syncthreads();

    // ---- 16 GRU steps ----
    for (int t = 0; t < TT; t++) {
        const uint32_t* hc  = hs[t & 1];
        uint32_t*       hnx = hs[(t + 1) & 1];

        float cr[4][4], cz[4][4], cn[4][4];
        #pragma unroll
        for (int m = 0; m < 4; m++)
            #pragma unroll
            for (int e = 0; e < 4; e++) { cr[m][e] = 0.f; cz[m][e] = 0.f; cn[m][e] = 0.f; }

        #pragma unroll
        for (int kt = 0; kt < 8; kt++) {
            #pragma unroll
            for (int m = 0; m < 4; m++) {
                int r0 = m * 16 + q;
                uint2 alo = *(const uint2*)(hc + r0 * HS + kt * 8 + 2 * p);
                uint2 ahi = *(const uint2*)(hc + (r0 + 8) * HS + kt * 8 + 2 * p);
                uint32_t a[4] = { alo.x, ahi.x, alo.y, ahi.y };
                mma8(cr[m], a, Br[kt]);
                mma8(cz[m], a, Bz[kt]);
                mma8(cn[m], a, Bn[kt]);
            }
        }

        // ---- activations (register elementwise; C-frag layout), STS.64 h writes ----
        #pragma unroll
        for (int m = 0; m < 4; m++) {
            int rlo = m * 16 + q;
            float2 xlo = *(const float2*)(xs + rlo * XS + t * 2);
            float2 xhi = *(const float2*)(xs + (rlo + 8) * XS + t * 2);
            #pragma unroll
            for (int hi = 0; hi < 2; hi++) {
                float x0 = hi ? xhi.x : xlo.x;
                float x1 = hi ? xhi.y : xlo.y;
                uint2 hpair;
                #pragma unroll
                for (int je = 0; je < 2; je++) {
                    int e2 = hi * 2 + je;
                    float ghr = cr[m][e2] + bh[0][je];
                    float ghz = cz[m][e2] + bh[1][je];
                    float ghn = cn[m][e2] + bh[2][je];
                    float xr  = fmaf(wi1[0][je], x1, fmaf(wi0[0][je], x0, bi[0][je]));
                    float xz  = fmaf(wi1[1][je], x1, fmaf(wi0[1][je], x0, bi[1][je]));
                    float xn  = fmaf(wi1[2][je], x1, fmaf(wi0[2][je], x0, bi[2][je]));
                    float r   = sig_ap(xr + ghr);
                    float z   = sig_ap(xz + ghz);
                    float nv  = tanh_ap(fmaf(r, ghn, xn));
                    float hp  = hreg[m][e2];
                    float hv  = fmaf(z, hp - nv, nv);
                    hreg[m][e2] = hv;
                    if (je == 0) hpair.x = f2tf(hv); else hpair.y = f2tf(hv);
                }
                int row = rlo + hi * 8;
                *(uint2*)(hnx + row * HS + w * 8 + 2 * p) = hpair;
            }
        }
        __syncthreads();
    }

    // ---- traj projection: tfeat[64,128] = h_last @ Wt^T + bt ----
    const uint32_t* hl = hs[0];

    uint32_t Bt[8][2][2];
    #pragma unroll
    for (int kt = 0; kt < 8; kt++)
        #pragma unroll
        for (int n2 = 0; n2 < 2; n2++) {
            int n = w * 16 + n2 * 8 + q;
            int k = kt * 8 + 2 * p;              // permuted-k
            Bt[kt][n2][0] = f2tf(Wt[n * HG + k]);
            Bt[kt][n2][1] = f2tf(Wt[n * HG + k + 1]);
        }

    float ct[4][2][4];
    #pragma unroll
    for (int m = 0; m < 4; m++)
        #pragma unroll
        for (int n2 = 0; n2 < 2; n2++)
            #pragma unroll
            for (int e = 0; e < 4; e++) ct[m][n2][e] = 0.f;

    #pragma unroll
    for (int kt = 0; kt < 8; kt++) {
        #pragma unroll
        for (int m = 0; m < 4; m++) {
            int r0 = m * 16 + q;
            uint2 alo = *(const uint2*)(hl + r0 * HS + kt * 8 + 2 * p);
            uint2 ahi = *(const uint2*)(hl + (r0 + 8) * HS + kt * 8 + 2 * p);
            uint32_t a[4] = { alo.x, ahi.x, alo.y, ahi.y };
            mma8(ct[m][0], a, Bt[kt][0]);
            mma8(ct[m][1], a, Bt[kt][1]);
        }
    }

    float btv[2][2];
    #pragma unroll
    for (int n2 = 0; n2 < 2; n2++)
        #pragma unroll
        for (int e = 0; e < 2; e++) btv[n2][e] = bt[w * 16 + n2 * 8 + 2 * p + e];

    // ---- stage tfeat through smem (reuse hs) for coalesced global stores ----
    __syncthreads();
    float* hf = (float*)hs;
    #pragma unroll
    for (int m = 0; m < 4; m++)
        #pragma unroll
        for (int n2 = 0; n2 < 2; n2++)
            #pragma unroll
            for (int hi = 0; hi < 2; hi++) {
                int row = m * 16 + q + hi * 8;
                int col = w * 16 + n2 * 8 + 2 * p;
                float2 v = make_float2(ct[m][n2][hi * 2 + 0] + btv[n2][0],
                                       ct[m][n2][hi * 2 + 1] + btv[n2][1]);
                *(float2*)(hf + (col >> 6) * (ROWS * HS) + row * HS + (col & 63)) = v;
            }
    __syncthreads();
    #pragma unroll
    for (int j = 0; j < 8; j++) {
        int i = tid + j * NTHR;
        int row = i >> 5, c4 = i & 31;
        int col = c4 * 4;
        float4 v = *(const float4*)(hf + (col >> 6) * (ROWS * HS) + row * HS + (col & 63));
        int gr = base + row;
        if (gr < B) *(float4*)(g_tfeat + (size_t)gr * HID + col) = v;
    }
}

// ===================== Kernel B: appear_proj + fuse + GELU =====================
__global__ void __launch_bounds__(NTHR, 1)
appear_fuse_kernel(const float* __restrict__ app,
                   const float* __restrict__ ba,
                   const float* __restrict__ bf,
                   float* __restrict__ out, int B)
{
    __shared__ __align__(16) uint32_t sm[2][ROWS * HS];   // 34816 B

    const int tid  = threadIdx.x;
    const int w    = tid >> 5;
    const int lane = tid & 31;
    const int q    = lane >> 2;
    const int p    = lane & 3;
    const int mw   = w >> 2;   // 0..1  (rows mw*32 .. +32)
    const int nw   = w & 3;    // 0..3  (cols nw*32 .. +32)
    const int base = blockIdx.x * ROWS;

    float4 pre[4];
    // ---- prefetch + fill chunk 0, prefetch chunk 1 ----
    #pragma unroll
    for (int j = 0; j < 4; j++) {
        int i = tid + j * NTHR; int row = i >> 4, c4 = i & 15;
        int gr = min(base + row, B - 1);
        pre[j] = *(const float4*)(app + (size_t)gr * APPD + 0 * 64 + c4 * 4);
    }
    #pragma unroll
    for (int j = 0; j < 4; j++) {
        int i = tid + j * NTHR; int row = i >> 4, c4 = i & 15;
        uint4 t4;
        t4.x = f2tf(pre[j].x); t4.y = f2tf(pre[j].y);
        t4.z = f2tf(pre[j].z); t4.w = f2tf(pre[j].w);
        *(uint4*)(&sm[0][row * HS + c4 * 4]) = t4;
    }
    #pragma unroll
    for (int j = 0; j < 4; j++) {
        int i = tid + j * NTHR; int row = i >> 4, c4 = i & 15;
        int gr = min(base + row, B - 1);
        pre[j] = *(const float4*)(app + (size_t)gr * APPD + 1 * 64 + c4 * 4);
    }
    __syncthreads();

    float cf[2][4][4];
    #pragma unroll
    for (int m = 0; m < 2; m++)
        #pragma unroll
        for (int n2 = 0; n2 < 4; n2++)
            #pragma unroll
            for (int e = 0; e < 4; e++) cf[m][n2][e] = 0.f;

    // ---- phase 1: appear GEMM over 8 chunks of K=64, double-buffered ----
    for (int c = 0; c < 8; c++) {
        if (c + 1 < 8) {
            #pragma unroll
            for (int j = 0; j < 4; j++) {
                int i = tid + j * NTHR; int row = i >> 4, c4 = i & 15;
                uint4 t4;
                t4.x = f2tf(pre[j].x); t4.y = f2tf(pre[j].y);
                t4.z = f2tf(pre[j].z); t4.w = f2tf(pre[j].w);
                *(uint4*)(&sm[(c + 1) & 1][row * HS + c4 * 4]) = t4;
            }
            if (c + 2 < 8) {
                #pragma unroll
                for (int j = 0; j < 4; j++) {
                    int i = tid + j * NTHR; int row = i >> 4, c4 = i & 15;
                    int gr = min(base + row, B - 1);
                    pre[j] = *(const float4*)(app + (size_t)gr * APPD + (c + 2) * 64 + c4 * 4);
                }
            }
        }
        const uint32_t* hb = sm[c & 1];
        #pragma unroll
        for (int kt = 0; kt < 8; kt++) {
            int ko = c * 8 + kt;
            uint4 w0 = *(const uint4*)(g_wa_sw + ((size_t)((ko * 4 + nw) * 2 + 0)) * 128 + lane * 4);
            uint4 w1 = *(const uint4*)(g_wa_sw + ((size_t)((ko * 4 + nw) * 2 + 1)) * 128 + lane * 4);
            uint32_t b0[2] = { w0.x, w0.y }, b1[2] = { w0.z, w0.w };
            uint32_t b2[2] = { w1.x, w1.y }, b3[2] = { w1.z, w1.w };
            #pragma unroll
            for (int m = 0; m < 2; m++) {
                int r0 = mw * 32 + m * 16 + q;
                uint2 alo = *(const uint2*)(hb + r0 * HS + kt * 8 + 2 * p);
                uint2 ahi = *(const uint2*)(hb + (r0 + 8) * HS + kt * 8 + 2 * p);
                uint32_t a[4] = { alo.x, ahi.x, alo.y, ahi.y };
                mma8(cf[m][0], a, b0);
                mma8(cf[m][1], a, b1);
                mma8(cf[m][2], a, b2);
                mma8(cf[m][3], a, b3);
            }
        }
        __syncthreads();
    }

    // ---- stage afeat (+ba) as tf32 into sm halves ----
    float bav[4][2];
    #pragma unroll
    for (int n2 = 0; n2 < 4; n2++)
        #pragma unroll
        for (int e = 0; e < 2; e++) bav[n2][e] = ba[nw * 32 + n2 * 8 + 2 * p + e];

    #pragma unroll
    for (int m = 0; m < 2; m++)
        #pragma unroll
        for (int n2 = 0; n2 < 4; n2++)
            #pragma unroll
            for (int hi = 0; hi < 2; hi++) {
                int row = mw * 32 + m * 16 + q + hi * 8;
                int col = nw * 32 + n2 * 8 + 2 * p;
                uint2 v;
                v.x = f2tf(cf[m][n2][hi * 2 + 0] + bav[n2][0]);
                v.y = f2tf(cf[m][n2][hi * 2 + 1] + bav[n2][1]);
                *(uint2*)(&sm[col >> 6][row * HS + (col & 63)]) = v;
            }
    __syncthreads();

    // ---- phase 2: fuse GEMM (pass 0: afeat cols 0..127; pass 1: tfeat) ----
    float cf2[2][4][4];
    #pragma unroll
    for (int m = 0; m < 2; m++)
        #pragma unroll
        for (int n2 = 0; n2 < 4; n2++)
            #pragma unroll
            for (int e = 0; e < 4; e++) cf2[m][n2][e] = 0.f;

    #pragma unroll
    for (int pass = 0; pass < 2; pass++) {
        #pragma unroll
        for (int kt = 0; kt < 16; kt++) {
            const uint32_t* hb = sm[kt >> 3];
            int kk = (kt & 7) * 8;
            int ko = pass * 16 + kt;
            uint4 w0 = *(const uint4*)(g_wf_sw + ((size_t)((ko * 4 + nw) * 2 + 0)) * 128 + lane * 4);
            uint4 w1 = *(const uint4*)(g_wf_sw + ((size_t)((ko * 4 + nw) * 2 + 1)) * 128 + lane * 4);
            uint32_t b0[2] = { w0.x, w0.y }, b1[2] = { w0.z, w0.w };
            uint32_t b2[2] = { w1.x, w1.y }, b3[2] = { w1.z, w1.w };
            #pragma unroll
            for (int m = 0; m < 2; m++) {
                int r0 = mw * 32 + m * 16 + q;
                uint2 alo = *(const uint2*)(hb + r0 * HS + kk + 2 * p);
                uint2 ahi = *(const uint2*)(hb + (r0 + 8) * HS + kk + 2 * p);
                uint32_t a[4] = { alo.x, ahi.x, alo.y, ahi.y };
                mma8(cf2[m][0], a, b0);
                mma8(cf2[m][1], a, b1);
                mma8(cf2[m][2], a, b2);
                mma8(cf2[m][3], a, b3);
            }
        }
        if (pass == 0) {
            __syncthreads();
            #pragma unroll
            for (int j = 0; j < 8; j++) {
                int i = tid + j * NTHR;
                int row = i >> 5, c4 = i & 31;
                int col = c4 * 4;
                int gr = min(base + row, B - 1);
                float4 v = *(const float4*)(g_tfeat + (size_t)gr * HID + col);
                uint4 t4;
                t4.x = f2tf(v.x); t4.y = f2tf(v.y);
                t4.z = f2tf(v.z); t4.w = f2tf(v.w);
                *(uint4*)(&sm[col >> 6][row * HS + (col & 63)]) = t4;
            }
            __syncthreads();
        }
    }

    // ---- bias + exact GELU, stage to smem, coalesced store ----
    float bfv[4][2];
    #pragma unroll
    for (int n2 = 0; n2 < 4; n2++)
        #pragma unroll
        for (int e = 0; e < 2; e++) bfv[n2][e] = bf[nw * 32 + n2 * 8 + 2 * p + e];

    __syncthreads();
    float* smf = (float*)sm;
    #pragma unroll
    for (int m = 0; m < 2; m++)
        #pragma unroll
        for (int n2 = 0; n2 < 4; n2++)
            #pragma unroll
            for (int hi = 0; hi < 2; hi++) {
                int row = mw * 32 + m * 16 + q + hi * 8;
                int col = nw * 32 + n2 * 8 + 2 * p;
                float x0 = cf2[m][n2][hi * 2 + 0] + bfv[n2][0];
                float x1 = cf2[m][n2][hi * 2 + 1] + bfv[n2][1];
                float2 v;
                v.x = 0.5f * x0 * (1.0f + erff(x0 * 0.70710678118654752f));
                v.y = 0.5f * x1 * (1.0f + erff(x1 * 0.70710678118654752f));
                *(float2*)(smf + (col >> 6) * (ROWS * HS) + row * HS + (col & 63)) = v;
            }
    __syncthreads();
    #pragma unroll
    for (int j = 0; j < 8; j++) {
        int i = tid + j * NTHR;
        int row = i >> 5, c4 = i & 31;
        int col = c4 * 4;
        float4 v = *(const float4*)(smf + (col >> 6) * (ROWS * HS) + row * HS + (col & 63));
        int gr = base + row;
        if (gr < B) *(float4*)(out + (size_t)gr * HID + col) = v;
    }
}

extern "C" void kernel_launch(void* const* d_in, const int* in_sizes, int n_in,
                              void* d_out, int out_size) {
    const float* app  = (const float*)d_in[0];   // [B,512]
    const float* cent = (const float*)d_in[1];   // [B,16,2]
    const float* Wih  = (const float*)d_in[2];   // [192,2]
    const float* Whh  = (const float*)d_in[3];   // [192,64]
    const float* bih  = (const float*)d_in[4];   // [192]
    const float* bhh  = (const float*)d_in[5];   // [192]
    const float* Wt   = (const float*)d_in[6];   // [128,64]
    const float* bt   = (const float*)d_in[7];   // [128]
    const float* Wa   = (const float*)d_in[8];   // [128,512]
    const float* ba   = (const float*)d_in[9];   // [128]
    const float* Wf   = (const float*)d_in[10];  // [128,256]
    const float* bf   = (const float*)d_in[11];  // [128]
    float* out = (float*)d_out;

    int B = in_sizes[0] / APPD;
    int nblk = (B + ROWS - 1) / ROWS;

    swizzle_wa_kernel<<<(HID * APPD + 255) / 256, 256>>>(Wa);
    swizzle_wf_kernel<<<(HID * 2 * HID + 255) / 256, 256>>>(Wf);
    gru_traj_kernel<<<nblk, NTHR>>>(cent, Wih, Whh, bih, bhh, Wt, bt, B);
    appear_fuse_kernel<<<nblk, NTHR>>>(app, ba, bf, out, B);
}